// round 14
// baseline (speedup 1.0000x reference)
#include <cuda_runtime.h>
#include <cuda_bf16.h>

// CRF NLL: B=512, S=1024, T=64.
// inputs: 0 emissions (B,S,T) f32, 1 tags (B,S) i32, 2 mask (B,S) i32,
//         3 start (T) f32, 4 end (T) f32, 5 transitions (T,T) f32
// output: scalar f32 = -(sum_b ll_b) / (sum_b L_b)
//
// Forward-backward split (Z = alpha_mid . beta_mid), scaled linear domain.
// The w-vector all-gather is done with SHFL.IDX (w fits in one 32-bit reg
// per lane as bf16x2) — no smem, no syncwarp in the hot loop. The g=0
// shuffle doubles as the rescale-exponent sample (k(w_{s-1}) applied at
// step s: stable frac recurrence). bf16 HFMA2 matvec, depth-4 accumulator
// chains, f32 commit (R8's proven path), emission exp one iteration ahead
// + 3-deep load queue. 8 warps/block x 128 blocks = 2 chains per SMSP.

#define B_ 512
#define S_ 1024
#define T_ 64
#define FULLMASK 0xffffffffu

__device__ float g_ll[B_];
__device__ float g_len[B_];

typedef __nv_bfloat162 bf2;

__device__ __forceinline__ bf2 bf2pack(float lo, float hi) {
    return __float22bfloat162_rn(make_float2(lo, hi));
}
__device__ __forceinline__ unsigned bf2bits(bf2 v) {
    return *(unsigned*)&v;
}
__device__ __forceinline__ bf2 bits2bf2(unsigned u) {
    bf2 v;
    *(unsigned*)&v = u;
    return v;
}

// 8 warps/block = 4 batches/block (fwd+bwd warp per batch). grid = 128.
__global__ void __launch_bounds__(256) crf_main(
    const float* __restrict__ emis,
    const int* __restrict__ tags,
    const int* __restrict__ mask,
    const float* __restrict__ start,
    const float* __restrict__ endt,
    const float* __restrict__ trans)
{
    __shared__ __align__(16) float sh_a[4][T_];      // forward's alpha_mid (f32)
    __shared__ float sh_sc[4][2];                    // [pair][{csF, numF}]

    const int lane = threadIdx.x & 31;
    const int wid  = threadIdx.x >> 5;
    const int pair = wid >> 1;      // 0..3
    const int role = wid & 1;       // 0 = forward, 1 = backward
    const int b    = blockIdx.x * 4 + pair;

    const int j0 = 2 * lane;
    const int j1 = j0 + 1;

    const int base = b * S_;
    const float* em = emis + (size_t)base * T_;
    const float2* ep = (const float2*)em;

    // ---- sequence length L (prefix mask) ----
    int lp = 0;
#pragma unroll 4
    for (int s = lane; s < S_; s += 32) lp += mask[base + s];
#pragma unroll
    for (int o = 16; o > 0; o >>= 1) lp += __shfl_xor_sync(FULLMASK, lp, o);
    const int L = lp;           // in [512, 1024]
    const int mid = L >> 1;     // >= 256

    const bf2 z2 = bf2pack(0.0f, 0.0f);

    if (role == 0) {
        // ================= FORWARD: alpha over s = 0..mid =================
        // Ej0[g] = bf16(E[2g][j0], E[2g+1][j0]); Ej1 likewise for col j1.
        bf2 Ej0[T_ / 2];
        bf2 Ej1[T_ / 2];
#pragma unroll
        for (int m = 0; m < T_ / 2; m++) {
            float2 ra = *(const float2*)&trans[(2 * m) * T_ + j0];
            float2 rb = *(const float2*)&trans[(2 * m + 1) * T_ + j0];
            Ej0[m] = bf2pack(__expf(ra.x), __expf(rb.x));
            Ej1[m] = bf2pack(__expf(ra.y), __expf(rb.y));
        }

        // numerator over s in [1, mid]
        float num = 0.0f;
        for (int s = 1 + lane; s <= mid; s += 32) {
            int tp = tags[base + s - 1];
            int tc = tags[base + s];
            num += trans[tp * T_ + tc] + em[s * T_ + tc];
        }
#pragma unroll
        for (int o = 16; o > 0; o >>= 1) num += __shfl_xor_sync(FULLMASK, num, o);
        if (lane == 0) {
            int tg0 = tags[base];
            num += start[tg0] + em[tg0];
        }

        // init: w_0 = exp(start + em_0)
        float2 e0 = ep[lane];
        float w0f = __expf(start[j0] + e0.x);
        float w1f = __expf(start[j1] + e0.y);
        bf2 w2 = bf2pack(w0f, w1f);

        // F one iteration ahead + 3-deep load queue.
        // entering iter s: F0/F1 = exp(em[s]); q1=em[s+1], q2=em[s+2], q3=em[s+3]
        float2 q1 = ep[1 * 32 + lane];
        float2 q2 = ep[2 * 32 + lane];
        float2 q3 = ep[3 * 32 + lane];
        float F0 = __expf(q1.x);
        float F1 = __expf(q1.y);
        q1 = q2; q2 = q3;
        q3 = ep[4 * 32 + lane];

        float csum = 0.0f;

        for (int s = 1; s <= mid; s++) {
            unsigned wu = bf2bits(w2);   // w_{s-1}, one reg per lane

            // gather lane0 first: doubles as rescale sample k(w_{s-1})
            unsigned uw0 = __shfl_sync(FULLMASK, wu, 0);
            int k = (int)((uw0 >> 7) & 0xff) - 127;   // bf16 exponent, low half
            k = max(-126, min(126, k));
            float r = __int_as_float((127 - k) << 23);

            // off-chain: next F, advance load queue (load em[s+4])
            float Fn0 = __expf(q1.x);
            float Fn1 = __expf(q1.y);
            q1 = q2; q2 = q3;
            q3 = ep[(s + 4) * 32 + lane];   // s+4 <= mid+4 <= 516 < S_

            // matvec via shfl all-gather: v[j] = sum_i w[i] * E[i][j]
            bf2 A0[8], A1[8];
#pragma unroll
            for (int a = 0; a < 8; a++) { A0[a] = z2; A1[a] = z2; }
            {
                bf2 ws = bits2bf2(uw0);
                A0[0] = __hfma2(ws, Ej0[0], A0[0]);
                A1[0] = __hfma2(ws, Ej1[0], A1[0]);
            }
#pragma unroll
            for (int g = 1; g < 32; g++) {
                bf2 ws = bits2bf2(__shfl_sync(FULLMASK, wu, g));
                A0[g & 7] = __hfma2(ws, Ej0[g], A0[g & 7]);
                A1[g & 7] = __hfma2(ws, Ej1[g], A1[g & 7]);
            }
            bf2 t0 = __hadd2(__hadd2(__hadd2(A0[0], A0[1]), __hadd2(A0[2], A0[3])),
                             __hadd2(__hadd2(A0[4], A0[5]), __hadd2(A0[6], A0[7])));
            bf2 t1 = __hadd2(__hadd2(__hadd2(A1[0], A1[1]), __hadd2(A1[2], A1[3])),
                             __hadd2(__hadd2(A1[4], A1[5]), __hadd2(A1[6], A1[7])));
            float2 f0 = __bfloat1622float2(t0);
            float2 f1 = __bfloat1622float2(t1);

            // commit (f32): w_s = sum * exp(em[s]) * 2^-k
            w0f = (f0.x + f0.y) * (F0 * r);
            w1f = (f1.x + f1.y) * (F1 * r);
            w2 = bf2pack(w0f, w1f);
            csum += (float)k;

            F0 = Fn0;
            F1 = Fn1;
        }

        // publish alpha_mid (scaled, f32) + scalars
        *(float2*)&sh_a[pair][j0] = make_float2(w0f, w1f);
        if (lane == 0) {
            sh_sc[pair][0] = csum;
            sh_sc[pair][1] = num;
        }
    } else {
        // ================= BACKWARD: beta over s = L-1..mid =================
        // Ri0[g] = bf16(E[j0][2g], E[j0][2g+1]); Ri1 likewise for row j1.
        bf2 Ri0[T_ / 2];
        bf2 Ri1[T_ / 2];
#pragma unroll
        for (int m = 0; m < T_ / 2; m++) {
            float2 ra = *(const float2*)&trans[j0 * T_ + 2 * m];
            float2 rb = *(const float2*)&trans[j1 * T_ + 2 * m];
            Ri0[m] = bf2pack(__expf(ra.x), __expf(ra.y));
            Ri1[m] = bf2pack(__expf(rb.x), __expf(rb.y));
        }

        // numerator over s in (mid, L)
        float num = 0.0f;
        for (int s = mid + 1 + lane; s < L; s += 32) {
            int tp = tags[base + s - 1];
            int tc = tags[base + s];
            num += trans[tp * T_ + tc] + em[s * T_ + tc];
        }
#pragma unroll
        for (int o = 16; o > 0; o >>= 1) num += __shfl_xor_sync(FULLMASK, num, o);
        if (lane == 0) {
            int tgl = tags[base + L - 1];
            num += endt[tgl];
        }

        // init: u_{L-1} = exp(end) o exp(em[L-1])  (exchange value)
        float2 eL = ep[(L - 1) * 32 + lane];
        float b0f = __expf(endt[j0]);
        float b1f = __expf(endt[j1]);
        bf2 u2 = bf2pack(b0f * __expf(eL.x), b1f * __expf(eL.y));

        // entering iter t: F0/F1 = exp(em[t]); q1=em[t-1], q2=em[t-2], q3=em[t-3]
        float2 q1 = ep[(L - 2) * 32 + lane];
        float2 q2 = ep[(L - 3) * 32 + lane];
        float2 q3 = ep[(L - 4) * 32 + lane];
        float F0 = __expf(q1.x);
        float F1 = __expf(q1.y);
        q1 = q2; q2 = q3;
        q3 = ep[(L - 5) * 32 + lane];   // L >= 512 -> safe

        float csum = 0.0f;

        for (int t = L - 2; t >= mid; t--) {
            unsigned uu = bf2bits(u2);   // u_{t+1} = beta_{t+1} o F_{t+1}

            unsigned uw0 = __shfl_sync(FULLMASK, uu, 0);
            int k = (int)((uw0 >> 7) & 0xff) - 127;
            k = max(-126, min(126, k));
            float r = __int_as_float((127 - k) << 23);

            // off-chain: next F (= exp(em[t-1])), advance queue (load em[t-4])
            float Fn0 = __expf(q1.x);
            float Fn1 = __expf(q1.y);
            q1 = q2; q2 = q3;
            int tl = t - 4; if (tl < 0) tl = 0;   // t >= mid >= 256: never taken
            q3 = ep[tl * 32 + lane];

            // matvec: v[i] = sum_j E[i][j] * u[j]
            bf2 A0[8], A1[8];
#pragma unroll
            for (int a = 0; a < 8; a++) { A0[a] = z2; A1[a] = z2; }
            {
                bf2 us = bits2bf2(uw0);
                A0[0] = __hfma2(us, Ri0[0], A0[0]);
                A1[0] = __hfma2(us, Ri1[0], A1[0]);
            }
#pragma unroll
            for (int g = 1; g < 32; g++) {
                bf2 us = bits2bf2(__shfl_sync(FULLMASK, uu, g));
                A0[g & 7] = __hfma2(us, Ri0[g], A0[g & 7]);
                A1[g & 7] = __hfma2(us, Ri1[g], A1[g & 7]);
            }
            bf2 t0 = __hadd2(__hadd2(__hadd2(A0[0], A0[1]), __hadd2(A0[2], A0[3])),
                             __hadd2(__hadd2(A0[4], A0[5]), __hadd2(A0[6], A0[7])));
            bf2 t1 = __hadd2(__hadd2(__hadd2(A1[0], A1[1]), __hadd2(A1[2], A1[3])),
                             __hadd2(__hadd2(A1[4], A1[5]), __hadd2(A1[6], A1[7])));
            float2 f0 = __bfloat1622float2(t0);
            float2 f1 = __bfloat1622float2(t1);

            // commit (f32): beta_t = sum * 2^-k; exchange u_t = beta_t o exp(em[t])
            b0f = (f0.x + f0.y) * r;
            b1f = (f1.x + f1.y) * r;
            u2 = bf2pack(b0f * F0, b1f * F1);
            csum += (float)k;

            F0 = Fn0;
            F1 = Fn1;
        }

        __syncthreads();

        // ---- join: Z = sum_i alpha_mid[i] * beta_mid[i] ----
        float2 a = *(const float2*)&sh_a[pair][j0];
        float e = a.x * b0f + a.y * b1f;
#pragma unroll
        for (int o = 16; o > 0; o >>= 1) e += __shfl_xor_sync(FULLMASK, e, o);
        if (lane == 0) {
            float csF  = sh_sc[pair][0];
            float numF = sh_sc[pair][1];
            float den = (float)(((double)csF + (double)csum) * 0.6931471805599453)
                        + __logf(e);
            g_ll[b]  = (numF + num) - den;
            g_len[b] = (float)L;
        }
        return;
    }
    // forward warps arrive here
    __syncthreads();
}

__global__ void crf_finalize(float* __restrict__ out) {
    __shared__ float s_ll[16];
    __shared__ float s_ln[16];
    int t = threadIdx.x;  // 512 threads
    float ll = g_ll[t];
    float ln = g_len[t];
#pragma unroll
    for (int o = 16; o > 0; o >>= 1) {
        ll += __shfl_xor_sync(FULLMASK, ll, o);
        ln += __shfl_xor_sync(FULLMASK, ln, o);
    }
    int w = t >> 5;
    if ((t & 31) == 0) { s_ll[w] = ll; s_ln[w] = ln; }
    __syncthreads();
    if (t == 0) {
        float sll = 0.0f, sln = 0.0f;
#pragma unroll
        for (int i = 0; i < 16; i++) { sll += s_ll[i]; sln += s_ln[i]; }
        out[0] = -(sll / sln);
    }
}

extern "C" void kernel_launch(void* const* d_in, const int* in_sizes, int n_in,
                              void* d_out, int out_size) {
    const float* emis  = (const float*)d_in[0];
    const int*   tags  = (const int*)d_in[1];
    const int*   mask  = (const int*)d_in[2];
    const float* start = (const float*)d_in[3];
    const float* endt  = (const float*)d_in[4];
    const float* trans = (const float*)d_in[5];
    float* out = (float*)d_out;

    crf_main<<<B_ / 4, 256>>>(emis, tags, mask, start, endt, trans);
    crf_finalize<<<1, B_>>>(out);
}